// round 1
// baseline (speedup 1.0000x reference)
#include <cuda_runtime.h>
#include <math.h>

#define EMB   1024
#define NH    16
#define DK    64
#define BB    2
#define SS    2048
#define NROW  (BB * SS)          // 4096

// ---------------- scratch (device globals: allocation-free) ----------------
__device__ float g_q[(size_t)NROW * EMB];
__device__ float g_k[(size_t)NROW * EMB];
__device__ float g_v[(size_t)NROW * EMB];
__device__ float g_o[(size_t)NROW * EMB];

// ---------------- GEMM: Y[M,N] = X[M,K] @ W[N,K]^T  (both row-major) -------
#define BM 64
#define BN 64
#define BKK 32

__global__ __launch_bounds__(256)
void gemm_xwt(const float* __restrict__ X, const float* __restrict__ W,
              float* __restrict__ Y, int M, int N, int K)
{
    __shared__ float Xs[BKK][BM + 4];
    __shared__ float Ws[BKK][BN + 4];

    const int tid = threadIdx.x;
    const int tx  = tid & 15;         // 0..15  (N dir)
    const int ty  = tid >> 4;         // 0..15  (M dir)
    const int rowBase = blockIdx.y * BM;
    const int colBase = blockIdx.x * BN;

    float acc[4][4] = {};

    for (int k0 = 0; k0 < K; k0 += BKK) {
        // load 64x32 tiles of X and W (K-contiguous, float4), store K-transposed
        #pragma unroll
        for (int i = 0; i < 2; i++) {
            int v  = tid + i * 256;       // 0..511
            int r  = v >> 3;              // tile row 0..63
            int kv = (v & 7) << 2;        // k offset 0,4,..,28
            float4 xv = *(const float4*)(X + (size_t)(rowBase + r) * K + k0 + kv);
            Xs[kv + 0][r] = xv.x; Xs[kv + 1][r] = xv.y;
            Xs[kv + 2][r] = xv.z; Xs[kv + 3][r] = xv.w;
            float4 wv = *(const float4*)(W + (size_t)(colBase + r) * K + k0 + kv);
            Ws[kv + 0][r] = wv.x; Ws[kv + 1][r] = wv.y;
            Ws[kv + 2][r] = wv.z; Ws[kv + 3][r] = wv.w;
        }
        __syncthreads();

        #pragma unroll
        for (int kk = 0; kk < BKK; kk++) {
            float a[4], b[4];
            #pragma unroll
            for (int i = 0; i < 4; i++) a[i] = Xs[kk][ty * 4 + i];
            #pragma unroll
            for (int j = 0; j < 4; j++) b[j] = Ws[kk][tx * 4 + j];
            #pragma unroll
            for (int i = 0; i < 4; i++)
                #pragma unroll
                for (int j = 0; j < 4; j++)
                    acc[i][j] += a[i] * b[j];
        }
        __syncthreads();
    }

    #pragma unroll
    for (int i = 0; i < 4; i++) {
        int r = rowBase + ty * 4 + i;
        float4 o = make_float4(acc[i][0], acc[i][1], acc[i][2], acc[i][3]);
        *(float4*)(Y + (size_t)r * N + colBase + tx * 4) = o;
    }
}

// ---------------- flash attention --------------------------------------
// grid: (S/64, NH, BB), block: 64 threads (1 thread = 1 query row)
// dyn smem layout (floats): Ks[64*64] | Vs[64*64] | Sc[64*65] | msk[64 ints]
#define ATTN_SMEM_FLOATS (4096 + 4096 + 64 * 65 + 64)
#define ATTN_SMEM_BYTES  (ATTN_SMEM_FLOATS * 4)

__global__ __launch_bounds__(64)
void attn_kernel(const int* __restrict__ mask)
{
    extern __shared__ float sm[];
    float* Ks  = sm;
    float* Vs  = sm + 4096;
    float* Sc  = sm + 8192;                 // stride 65 per row
    int*   msk = (int*)(sm + 8192 + 64 * 65);

    const int qt = blockIdx.x;
    const int h  = blockIdx.y;
    const int b  = blockIdx.z;
    const int t  = threadIdx.x;             // 0..63

    // ---- stage Q tile coalesced into Ks buffer, then copy to registers ----
    const float* qb = g_q + (size_t)(b * SS + qt * 64) * EMB + h * DK;
    #pragma unroll
    for (int i = 0; i < 16; i++) {
        int v  = t + i * 64;                // 0..1023
        int r  = v >> 4;
        int dv = (v & 15) << 2;
        *(float4*)&Ks[r * 64 + dv] = *(const float4*)(qb + (size_t)r * EMB + dv);
    }
    __syncthreads();
    float qreg[64];
    #pragma unroll
    for (int d = 0; d < 64; d++) qreg[d] = Ks[t * 64 + d];
    __syncthreads();

    float acc[64];
    #pragma unroll
    for (int d = 0; d < 64; d++) acc[d] = 0.f;
    float m = -INFINITY, l = 0.f;

    const int nkt = SS / 64;                // 32 key tiles
    for (int kt = 0; kt < nkt; kt++) {
        const float* kb = g_k + (size_t)(b * SS + kt * 64) * EMB + h * DK;
        const float* vb = g_v + (size_t)(b * SS + kt * 64) * EMB + h * DK;
        #pragma unroll
        for (int i = 0; i < 16; i++) {
            int v  = t + i * 64;
            int r  = v >> 4;
            int dv = (v & 15) << 2;
            *(float4*)&Ks[r * 64 + dv] = *(const float4*)(kb + (size_t)r * EMB + dv);
            *(float4*)&Vs[r * 64 + dv] = *(const float4*)(vb + (size_t)r * EMB + dv);
        }
        msk[t] = mask[b * SS + kt * 64 + t];
        __syncthreads();

        // scores for this thread's query row
        float tmax = -INFINITY;
        #pragma unroll 4
        for (int j = 0; j < 64; j++) {
            float s0 = 0.f, s1 = 0.f, s2 = 0.f, s3 = 0.f;
            const float* kr = &Ks[j * 64];
            #pragma unroll
            for (int d = 0; d < 64; d += 4) {
                s0 += qreg[d + 0] * kr[d + 0];
                s1 += qreg[d + 1] * kr[d + 1];
                s2 += qreg[d + 2] * kr[d + 2];
                s3 += qreg[d + 3] * kr[d + 3];
            }
            float s = (s0 + s1) + (s2 + s3);
            s *= 0.125f;                           // 1/sqrt(64)
            if (msk[j] != 0) s = -1e9f;            // key-padding mask (replace)
            Sc[t * 65 + j] = s;
            tmax = fmaxf(tmax, s);
        }

        float newm = fmaxf(m, tmax);
        float corr = __expf(m - newm);             // exp(-inf)=0 on first tile
        l *= corr;
        #pragma unroll
        for (int d = 0; d < 64; d++) acc[d] *= corr;

        for (int j = 0; j < 64; j++) {
            float p = __expf(Sc[t * 65 + j] - newm);
            l += p;
            const float* vr = &Vs[j * 64];
            #pragma unroll
            for (int d = 0; d < 64; d++) acc[d] += p * vr[d];
        }
        m = newm;
        __syncthreads();
    }

    // ---- normalize, stage to smem, coalesced store ----
    float inv_l = 1.0f / l;
    #pragma unroll
    for (int d = 0; d < 64; d++) Sc[t * 65 + d] = acc[d] * inv_l;
    __syncthreads();

    float* ob = g_o + (size_t)(b * SS + qt * 64) * EMB + h * DK;
    #pragma unroll
    for (int i = 0; i < 16; i++) {
        int v  = t + i * 64;
        int r  = v >> 4;
        int dv = (v & 15) << 2;
        float4 val = make_float4(Sc[r * 65 + dv + 0], Sc[r * 65 + dv + 1],
                                 Sc[r * 65 + dv + 2], Sc[r * 65 + dv + 3]);
        *(float4*)(ob + (size_t)r * EMB + dv) = val;
    }
}

// ---------------- launch --------------------------------------------------
extern "C" void kernel_launch(void* const* d_in, const int* in_sizes, int n_in,
                              void* d_out, int out_size)
{
    const float* x    = (const float*)d_in[0];
    const int*   mask = (const int*)d_in[1];   // nonzero-word test: robust to i32/f32 bool
    const float* wq   = (const float*)d_in[2];
    const float* wk   = (const float*)d_in[3];
    const float* wv   = (const float*)d_in[4];
    const float* wo   = (const float*)d_in[5];
    float* out = (float*)d_out;

    float *q, *k, *v, *o;
    cudaGetSymbolAddress((void**)&q, g_q);
    cudaGetSymbolAddress((void**)&k, g_k);
    cudaGetSymbolAddress((void**)&v, g_v);
    cudaGetSymbolAddress((void**)&o, g_o);

    dim3 gg(EMB / BN, NROW / BM);   // (16, 64)
    gemm_xwt<<<gg, 256>>>(x, wq, q, NROW, EMB, EMB);
    gemm_xwt<<<gg, 256>>>(x, wk, k, NROW, EMB, EMB);
    gemm_xwt<<<gg, 256>>>(x, wv, v, NROW, EMB, EMB);

    cudaFuncSetAttribute(attn_kernel, cudaFuncAttributeMaxDynamicSharedMemorySize,
                         ATTN_SMEM_BYTES);
    attn_kernel<<<dim3(SS / 64, NH, BB), 64, ATTN_SMEM_BYTES>>>(mask);

    gemm_xwt<<<gg, 256>>>(o, wo, out, NROW, EMB, EMB);
}